// round 16
// baseline (speedup 1.0000x reference)
#include <cuda_runtime.h>
#include <cuda_bf16.h>
#include <math.h>
#include <stdint.h>

// Problem constants
#define B_   2
#define N_   1024
#define D_   2048
#define H_   8
#define I_   4
#define KD_  128
#define VD_  128
#define HI_  32    // H_*I_
#define QKV_W 6144  // 4096 q + 1024 k + 1024 v

// Postproc dispatch ranges
#define QTOT  (B_ * N_ * HI_ * 64)       // 4,194,304
#define KTOT  (B_ * N_ * H_ * 64)        // 1,048,576
#define VTOT4 (B_ * N_ * H_ * VD_ / 4)   //   524,288
#define PPTOT (QTOT + KTOT + VTOT4)

// ---------------------------------------------------------------------------
// Device scratch
// ---------------------------------------------------------------------------
__device__ float g_qkv[(size_t)B_ * N_ * QKV_W];          // fused q|k|v fp32
__device__ __nv_bfloat16 g_xh[(size_t)B_ * N_ * D_];
__device__ __nv_bfloat16 g_xl[(size_t)B_ * N_ * D_];
__device__ __nv_bfloat16 g_wallh[(size_t)D_ * QKV_W];     // fused Wq|Wk|Wv
__device__ __nv_bfloat16 g_walll[(size_t)D_ * QKV_W];
__device__ __nv_bfloat16 g_woh[(size_t)HI_ * VD_ * D_];
__device__ __nv_bfloat16 g_wol[(size_t)HI_ * VD_ * D_];
__device__ __nv_bfloat16 g_qh[(size_t)B_ * N_ * HI_ * KD_];
__device__ __nv_bfloat16 g_ql[(size_t)B_ * N_ * HI_ * KD_];
__device__ __nv_bfloat16 g_kh[(size_t)B_ * N_ * H_ * KD_];
__device__ __nv_bfloat16 g_kl[(size_t)B_ * N_ * H_ * KD_];
__device__ __nv_bfloat16 g_vh[(size_t)B_ * N_ * H_ * VD_];
__device__ __nv_bfloat16 g_vl[(size_t)B_ * N_ * H_ * VD_];
__device__ __nv_bfloat16 g_ah[(size_t)B_ * N_ * HI_ * VD_];
__device__ __nv_bfloat16 g_al[(size_t)B_ * N_ * HI_ * VD_];

// ---------------------------------------------------------------------------
// Helpers
// ---------------------------------------------------------------------------
__device__ __forceinline__ void ldsm4(uint32_t* r, const __nv_bfloat16* p) {
    uint32_t a = (uint32_t)__cvta_generic_to_shared(p);
    asm volatile("ldmatrix.sync.aligned.m8n8.x4.shared.b16 {%0,%1,%2,%3}, [%4];"
                 : "=r"(r[0]), "=r"(r[1]), "=r"(r[2]), "=r"(r[3]) : "r"(a));
}
__device__ __forceinline__ void ldsm4t(uint32_t* r, const __nv_bfloat16* p) {
    uint32_t a = (uint32_t)__cvta_generic_to_shared(p);
    asm volatile("ldmatrix.sync.aligned.m8n8.x4.trans.shared.b16 {%0,%1,%2,%3}, [%4];"
                 : "=r"(r[0]), "=r"(r[1]), "=r"(r[2]), "=r"(r[3]) : "r"(a));
}
__device__ __forceinline__ void mma16816(float* c, const uint32_t* a, const uint32_t* b) {
    asm volatile("mma.sync.aligned.m16n8k16.row.col.f32.bf16.bf16.f32 "
                 "{%0,%1,%2,%3}, {%4,%5,%6,%7}, {%8,%9}, {%0,%1,%2,%3};"
                 : "+f"(c[0]), "+f"(c[1]), "+f"(c[2]), "+f"(c[3])
                 : "r"(a[0]), "r"(a[1]), "r"(a[2]), "r"(a[3]),
                   "r"(b[0]), "r"(b[1]));
}
__device__ __forceinline__ uint32_t packbf(float a, float b) {
    __nv_bfloat162 t = __floats2bfloat162_rn(a, b);
    return *(uint32_t*)&t;
}
__device__ __forceinline__ void cp16s(uint32_t s, const void* g) {
    asm volatile("cp.async.cg.shared.global [%0], [%1], 16;" :: "r"(s), "l"(g));
}
#define CP_COMMIT() asm volatile("cp.async.commit_group;" ::: "memory")
#define CP_WAIT(n)  asm volatile("cp.async.wait_group %0;" :: "n"(n) : "memory")

// ---------------------------------------------------------------------------
// fp32 -> bf16 hi/lo split (coalesced: one float4 per thread)
// ---------------------------------------------------------------------------
__device__ __forceinline__ void split_one(float4 v, __nv_bfloat16* oh,
                                          __nv_bfloat16* ol, size_t o)
{
    __nv_bfloat16 h0 = __float2bfloat16(v.x);
    __nv_bfloat16 h1 = __float2bfloat16(v.y);
    __nv_bfloat16 h2 = __float2bfloat16(v.z);
    __nv_bfloat16 h3 = __float2bfloat16(v.w);
    __nv_bfloat162 hp0; hp0.x = h0; hp0.y = h1;
    __nv_bfloat162 hp1; hp1.x = h2; hp1.y = h3;
    *(uint2*)(oh + o) = make_uint2(*(uint32_t*)&hp0, *(uint32_t*)&hp1);
    *(uint2*)(ol + o) = make_uint2(
        packbf(v.x - __bfloat162float(h0), v.y - __bfloat162float(h1)),
        packbf(v.z - __bfloat162float(h2), v.w - __bfloat162float(h3)));
}

__global__ void split4_kernel(const float4* __restrict__ in,
                              __nv_bfloat16* __restrict__ oh,
                              __nv_bfloat16* __restrict__ ol, int total4)
{
    int i = blockIdx.x * blockDim.x + threadIdx.x;
    if (i >= total4) return;
    split_one(in[i], oh, ol, (size_t)i * 4);
}

// Split + place into wider fused matrix at column offset (coalesced)
__global__ void splitcat4_kernel(const float* __restrict__ in,
                                 __nv_bfloat16* __restrict__ oh,
                                 __nv_bfloat16* __restrict__ ol,
                                 int srcW, int dstW, int colofs, int total4)
{
    int i = blockIdx.x * blockDim.x + threadIdx.x;
    if (i >= total4) return;
    int w4  = srcW >> 2;
    int row = i / w4;
    int c4  = i - row * w4;
    float4 v = *(const float4*)(in + (size_t)row * srcW + c4 * 4);
    split_one(v, oh, ol, (size_t)row * dstW + colofs + c4 * 4);
}

// ---------------------------------------------------------------------------
// Split-bf16 GEMM, 3-stage cp.async pipeline (plain fp32 C store).
// BM=BN=128, BK=32, 256 threads, 8 warps (4m x 2n), warp tile 32x64.
// OCCUPANCY 2: 2 CTAs/SM so one CTA's sync/cp.async bubbles are filled by
// the other's HMMA stream.
// ---------------------------------------------------------------------------
#define ASTR 40
#define BSTR 136
#define GSTAGE (128*ASTR*2 + 32*BSTR*2)          // bf16 elems per stage (18944)
#define GEMM_SMEM_BYTES (GSTAGE * 3 * 2)         // 113,664 B

__global__ __launch_bounds__(256, 2) void bgemm3_kernel(
    const __nv_bfloat16* __restrict__ Ah_g, const __nv_bfloat16* __restrict__ Al_g,
    const __nv_bfloat16* __restrict__ Bh_g, const __nv_bfloat16* __restrict__ Bl_g,
    float* __restrict__ C, int M, int Nc, int Kd)
{
    extern __shared__ __nv_bfloat16 sm[];

    const int tid    = threadIdx.x;
    const int lane   = tid & 31;
    const int wid    = tid >> 5;
    const int warp_m = wid & 3;
    const int warp_n = wid >> 2;
    const int brow   = blockIdx.y * 128;
    const int bcol   = blockIdx.x * 128;
    const int lr = lane & 15;
    const int lc = (lane >> 4) << 3;

    __nv_bfloat16* sAh[3]; __nv_bfloat16* sAl[3];
    __nv_bfloat16* sBh[3]; __nv_bfloat16* sBl[3];
    #pragma unroll
    for (int s = 0; s < 3; s++) {
        __nv_bfloat16* base = sm + s * GSTAGE;
        sAh[s] = base;
        sAl[s] = base + 128 * ASTR;
        sBh[s] = base + 128 * ASTR * 2;
        sBl[s] = base + 128 * ASTR * 2 + 32 * BSTR;
    }

    auto load_stage = [&](int s, int k0) {
        #pragma unroll
        for (int p = 0; p < 2; p++) {
            int i = p * 256 + tid;
            int r = i >> 2, cc = (i & 3) << 3;
            size_t g = (size_t)(brow + r) * Kd + k0 + cc;
            cp16s((uint32_t)__cvta_generic_to_shared(sAh[s] + r * ASTR + cc), Ah_g + g);
            cp16s((uint32_t)__cvta_generic_to_shared(sAl[s] + r * ASTR + cc), Al_g + g);
        }
        #pragma unroll
        for (int p = 0; p < 2; p++) {
            int i = p * 256 + tid;
            int r = i >> 4, cc = (i & 15) << 3;
            size_t g = (size_t)(k0 + r) * Nc + bcol + cc;
            cp16s((uint32_t)__cvta_generic_to_shared(sBh[s] + r * BSTR + cc), Bh_g + g);
            cp16s((uint32_t)__cvta_generic_to_shared(sBl[s] + r * BSTR + cc), Bl_g + g);
        }
    };

    float acc[2][8][4];
    #pragma unroll
    for (int im = 0; im < 2; im++)
        #pragma unroll
        for (int jn = 0; jn < 8; jn++)
            #pragma unroll
            for (int t = 0; t < 4; t++) acc[im][jn][t] = 0.f;

    const int nk = Kd >> 5;
    load_stage(0, 0);
    CP_COMMIT();
    load_stage(1, 32);
    CP_COMMIT();

    for (int kt = 0; kt < nk; kt++) {
        const int s = kt % 3;
        // Stage kt's group must be complete; final iteration drains all.
        if (kt + 1 < nk) { CP_WAIT(1); } else { CP_WAIT(0); }
        __syncthreads();
        if (kt + 2 < nk) {
            load_stage((kt + 2) % 3, (kt + 2) << 5);
            CP_COMMIT();
        }

        #pragma unroll
        for (int ks = 0; ks < 2; ks++) {
            uint32_t ah[2][4], al[2][4];
            #pragma unroll
            for (int im = 0; im < 2; im++) {
                const int ar = (warp_m * 32 + im * 16 + lr) * ASTR + ks * 16 + lc;
                ldsm4(ah[im], sAh[s] + ar);
                ldsm4(al[im], sAl[s] + ar);
            }
            #pragma unroll
            for (int jp = 0; jp < 4; jp++) {
                uint32_t bh[4], bl[4];
                const int boff = (ks * 16 + lr) * BSTR + warp_n * 64 + jp * 16 + lc;
                ldsm4t(bh, sBh[s] + boff);
                ldsm4t(bl, sBl[s] + boff);
                #pragma unroll
                for (int im = 0; im < 2; im++) {
                    mma16816(acc[im][jp * 2 + 0], ah[im], bh + 0);
                    mma16816(acc[im][jp * 2 + 1], ah[im], bh + 2);
                    mma16816(acc[im][jp * 2 + 0], ah[im], bl + 0);
                    mma16816(acc[im][jp * 2 + 1], ah[im], bl + 2);
                    mma16816(acc[im][jp * 2 + 0], al[im], bh + 0);
                    mma16816(acc[im][jp * 2 + 1], al[im], bh + 2);
                }
            }
        }
    }

    const int r0 = lane >> 2;
    const int c0 = (lane & 3) << 1;
    #pragma unroll
    for (int im = 0; im < 2; im++) {
        #pragma unroll
        for (int jn = 0; jn < 8; jn++) {
            float* cp = C + (size_t)(brow + warp_m * 32 + im * 16 + r0) * Nc
                          + bcol + warp_n * 64 + jn * 8 + c0;
            *(float2*)cp              = make_float2(acc[im][jn][0], acc[im][jn][1]);
            *(float2*)(cp + 8 * (size_t)Nc) = make_float2(acc[im][jn][2], acc[im][jn][3]);
        }
    }
}

// ---------------------------------------------------------------------------
// Merged post-processing: RoPE+split for q and k, plain split for v.
// One launch; dispatch by global thread id range.
// ---------------------------------------------------------------------------
__device__ __forceinline__ void rope_one(const float* __restrict__ qkv,
                                         __nv_bfloat16* __restrict__ oh,
                                         __nv_bfloat16* __restrict__ ol,
                                         int idx, int nheads, int colofs,
                                         float outscale)
{
    int j    = idx & 63;
    int t    = idx >> 6;
    int head = t % nheads;
    int row  = t / nheads;
    int n    = row & (N_ - 1);

    // theta^(-j/64) computed via exp2 (log2(10000)/64 = 0.2076205059...)
    float inv = exp2f((float)j * -0.20762050593045889f);
    float ang = (float)n * inv;
    float s, c;
    sincosf(ang, &s, &c);

    const float* p = qkv + (size_t)row * QKV_W + colofs + head * 128;
    float x1 = p[j];
    float x2 = p[j + 64];
    float r1 = (x1 * c - x2 * s) * outscale;
    float r2 = (x1 * s + x2 * c) * outscale;

    size_t ob = ((size_t)row * nheads + head) * 128;
    __nv_bfloat16 h1 = __float2bfloat16(r1);
    __nv_bfloat16 h2 = __float2bfloat16(r2);
    oh[ob + j]      = h1;
    oh[ob + j + 64] = h2;
    ol[ob + j]      = __float2bfloat16(r1 - __bfloat162float(h1));
    ol[ob + j + 64] = __float2bfloat16(r2 - __bfloat162float(h2));
}

__global__ void postproc_kernel(const float* __restrict__ qkv,
                                __nv_bfloat16* __restrict__ qh,
                                __nv_bfloat16* __restrict__ ql,
                                __nv_bfloat16* __restrict__ kh,
                                __nv_bfloat16* __restrict__ kl,
                                __nv_bfloat16* __restrict__ vh,
                                __nv_bfloat16* __restrict__ vl,
                                float qscale)
{
    int gid = blockIdx.x * blockDim.x + threadIdx.x;
    if (gid < QTOT) {
        rope_one(qkv, qh, ql, gid, HI_, 0, qscale);
    } else if (gid < QTOT + KTOT) {
        rope_one(qkv, kh, kl, gid - QTOT, H_, 4096, 1.0f);
    } else if (gid < PPTOT) {
        int idx = gid - QTOT - KTOT;
        int row = idx >> 8;            // 256 float4 per v row (1024 floats)
        int c4  = (idx & 255) << 2;
        float4 v = *(const float4*)(qkv + (size_t)row * QKV_W + 5120 + c4);
        split_one(v, vh, vl, (size_t)row * 1024 + c4);
    }
}

// ---------------------------------------------------------------------------
// Tensor-core flash attention (HMMA). BM=128, BN=64, d=128, causal.
// K/V double-buffered via cp.async.
// ---------------------------------------------------------------------------
#define QSTR 136
#define KSTR 136
#define VSTR 136
#define KVSTG (4 * 64 * 136)
#define FLASH3_SMEM_BYTES ((2*128*QSTR + 2*KVSTG) * 2)

__global__ __launch_bounds__(256) void flash_mma_kernel(
    const __nv_bfloat16* __restrict__ qh, const __nv_bfloat16* __restrict__ ql,
    const __nv_bfloat16* __restrict__ kh, const __nv_bfloat16* __restrict__ kl,
    const __nv_bfloat16* __restrict__ vh, const __nv_bfloat16* __restrict__ vl,
    __nv_bfloat16* __restrict__ oh, __nv_bfloat16* __restrict__ ol)
{
    extern __shared__ __nv_bfloat16 smb[];
    __nv_bfloat16* QH  = smb;
    __nv_bfloat16* QL  = QH + 128 * QSTR;
    __nv_bfloat16* KV0 = QL + 128 * QSTR;

    const int tid  = threadIdx.x;
    const int lane = tid & 31;
    const int w    = tid >> 5;
    const int qt   = gridDim.x - 1 - blockIdx.x;
    const int bhi  = blockIdx.y;
    const int b    = bhi >> 5;
    const int hi   = bhi & 31;
    const int h    = hi >> 2;

    const int lr = lane & 15;
    const int lc = (lane >> 4) << 3;
    const uint32_t kvu = (uint32_t)__cvta_generic_to_shared(KV0);

    const uint32_t KLOFS = 64 * 136 * 2;
    const uint32_t VHOFS = 2 * KLOFS;
    const uint32_t VLOFS = 3 * KLOFS;
    const uint32_t KVSTB = 4 * KLOFS;

    auto load_kv = [&](int s, int kt) {
        #pragma unroll
        for (int p = 0; p < 4; p++) {
            int i = p * 256 + tid;
            int r = i >> 4, cb = (i & 15) << 4;
            size_t g = ((size_t)(b * N_ + kt * 64 + r) * H_ + h) * 128 + (cb >> 1);
            uint32_t bs = kvu + s * KVSTB + r * 272 + cb;
            cp16s(bs, kh + g);
            cp16s(bs + KLOFS, kl + g);
            cp16s(bs + VHOFS, vh + g);
            cp16s(bs + VLOFS, vl + g);
        }
    };

    const size_t qrow0 = (size_t)(b * N_ + qt * 128) * HI_ + hi;
    for (int i = tid; i < 128 * 16; i += 256) {
        int r = i >> 4, cb = i & 15;
        size_t g = (qrow0 + (size_t)r * HI_) * KD_;
        *(uint4*)(QH + r * QSTR + cb * 8) = *((const uint4*)(qh + g) + cb);
        *(uint4*)(QL + r * QSTR + cb * 8) = *((const uint4*)(ql + g) + cb);
    }

    float m0 = -1e30f, m1 = -1e30f, l0 = 0.f, l1 = 0.f;
    float oacc[16][4];
    #pragma unroll
    for (int nt = 0; nt < 16; nt++)
        #pragma unroll
        for (int t = 0; t < 4; t++) oacc[nt][t] = 0.f;

    const int row0 = qt * 128 + w * 16 + (lane >> 2);
    const int ktmax = 2 * qt + 1;

    load_kv(0, 0);
    CP_COMMIT();

    for (int kt = 0; kt <= ktmax; kt++) {
        const int s = kt & 1;
        if (kt < ktmax) {
            load_kv(s ^ 1, kt + 1);
            CP_COMMIT();
            CP_WAIT(1);
        } else {
            CP_WAIT(0);
        }
        __syncthreads();

        __nv_bfloat16* KH = KV0 + s * KVSTG;
        __nv_bfloat16* KL = KH + 64 * 136;
        __nv_bfloat16* VH = KL + 64 * 136;
        __nv_bfloat16* VL = VH + 64 * 136;

        const bool skip = (kt * 64) > (qt * 128 + w * 16 + 15);
        if (!skip) {
            float sacc[8][4];
            #pragma unroll
            for (int j = 0; j < 8; j++)
                #pragma unroll
                for (int t = 0; t < 4; t++) sacc[j][t] = 0.f;

            #pragma unroll
            for (int ks = 0; ks < 8; ks++) {
                uint32_t ah[4], al[4];
                ldsm4(ah, &QH[(w * 16 + lr) * QSTR + ks * 16 + lc]);
                ldsm4(al, &QL[(w * 16 + lr) * QSTR + ks * 16 + lc]);
                #pragma unroll
                for (int nb = 0; nb < 4; nb++) {
                    uint32_t bhk[4], blk[4];
                    ldsm4(bhk, &KH[(nb * 16 + lr) * KSTR + ks * 16 + lc]);
                    ldsm4(blk, &KL[(nb * 16 + lr) * KSTR + ks * 16 + lc]);
                    uint32_t beh[2] = {bhk[0], bhk[2]};
                    uint32_t boh[2] = {bhk[1], bhk[3]};
                    uint32_t bel[2] = {blk[0], blk[2]};
                    uint32_t bol[2] = {blk[1], blk[3]};
                    mma16816(sacc[2 * nb + 0], ah, beh);
                    mma16816(sacc[2 * nb + 0], al, beh);
                    mma16816(sacc[2 * nb + 0], ah, bel);
                    mma16816(sacc[2 * nb + 1], ah, boh);
                    mma16816(sacc[2 * nb + 1], al, boh);
                    mma16816(sacc[2 * nb + 1], ah, bol);
                }
            }

            if (kt >= 2 * qt) {
                #pragma unroll
                for (int j = 0; j < 8; j++) {
                    int col = kt * 64 + j * 8 + 2 * (lane & 3);
                    if (col     > row0)     sacc[j][0] = -1e30f;
                    if (col + 1 > row0)     sacc[j][1] = -1e30f;
                    if (col     > row0 + 8) sacc[j][2] = -1e30f;
                    if (col + 1 > row0 + 8) sacc[j][3] = -1e30f;
                }
            }

            float tm0 = -1e30f, tm1 = -1e30f;
            #pragma unroll
            for (int j = 0; j < 8; j++) {
                tm0 = fmaxf(tm0, fmaxf(sacc[j][0], sacc[j][1]));
                tm1 = fmaxf(tm1, fmaxf(sacc[j][2], sacc[j][3]));
            }
            tm0 = fmaxf(tm0, __shfl_xor_sync(0xffffffffu, tm0, 1));
            tm0 = fmaxf(tm0, __shfl_xor_sync(0xffffffffu, tm0, 2));
            tm1 = fmaxf(tm1, __shfl_xor_sync(0xffffffffu, tm1, 1));
            tm1 = fmaxf(tm1, __shfl_xor_sync(0xffffffffu, tm1, 2));

            float mn0 = fmaxf(m0, tm0), mn1 = fmaxf(m1, tm1);
            float al0 = exp2f(m0 - mn0), al1 = exp2f(m1 - mn1);
            m0 = mn0; m1 = mn1;

            float rs0 = 0.f, rs1 = 0.f;
            uint32_t pah[4][4], pal[4][4];
            #pragma unroll
            for (int j = 0; j < 8; j++) {
                float p0 = exp2f(sacc[j][0] - mn0);
                float p1 = exp2f(sacc[j][1] - mn0);
                float p2 = exp2f(sacc[j][2] - mn1);
                float p3 = exp2f(sacc[j][3] - mn1);
                rs0 += p0 + p1;
                rs1 += p2 + p3;
                __nv_bfloat16 h0 = __float2bfloat16(p0);
                __nv_bfloat16 h1 = __float2bfloat16(p1);
                __nv_bfloat16 h2 = __float2bfloat16(p2);
                __nv_bfloat16 h3 = __float2bfloat16(p3);
                int kk = j >> 1, odd = j & 1;
                __nv_bfloat162 ph01; ph01.x = h0; ph01.y = h1;
                __nv_bfloat162 ph23; ph23.x = h2; ph23.y = h3;
                pah[kk][odd * 2 + 0] = *(uint32_t*)&ph01;
                pah[kk][odd * 2 + 1] = *(uint32_t*)&ph23;
                pal[kk][odd * 2 + 0] = packbf(p0 - __bfloat162float(h0),
                                              p1 - __bfloat162float(h1));
                pal[kk][odd * 2 + 1] = packbf(p2 - __bfloat162float(h2),
                                              p3 - __bfloat162float(h3));
            }
            rs0 += __shfl_xor_sync(0xffffffffu, rs0, 1);
            rs0 += __shfl_xor_sync(0xffffffffu, rs0, 2);
            rs1 += __shfl_xor_sync(0xffffffffu, rs1, 1);
            rs1 += __shfl_xor_sync(0xffffffffu, rs1, 2);
            l0 = al0 * l0 + rs0;
            l1 = al1 * l1 + rs1;

            #pragma unroll
            for (int nt = 0; nt < 16; nt++) {
                oacc[nt][0] *= al0; oacc[nt][1] *= al0;
                oacc[nt][2] *= al1; oacc[nt][3] *= al1;
            }

            #pragma unroll
            for (int kk = 0; kk < 4; kk++) {
                #pragma unroll
                for (int jp = 0; jp < 8; jp++) {
                    uint32_t vhr[4], vlr[4];
                    ldsm4t(vhr, &VH[(kk * 16 + lr) * VSTR + jp * 16 + lc]);
                    ldsm4t(vlr, &VL[(kk * 16 + lr) * VSTR + jp * 16 + lc]);
                    mma16816(oacc[2 * jp + 0], pah[kk], vhr + 0);
                    mma16816(oacc[2 * jp + 0], pal[kk], vhr + 0);
                    mma16816(oacc[2 * jp + 0], pah[kk], vlr + 0);
                    mma16816(oacc[2 * jp + 1], pah[kk], vhr + 2);
                    mma16816(oacc[2 * jp + 1], pal[kk], vhr + 2);
                    mma16816(oacc[2 * jp + 1], pah[kk], vlr + 2);
                }
            }
        }
        __syncthreads();
    }

    float inv0 = 1.f / l0, inv1 = 1.f / l1;
    const int c0 = 2 * (lane & 3);
    #pragma unroll
    for (int nt = 0; nt < 16; nt++) {
        size_t r0g = ((size_t)(b * N_ + row0) * HI_ + hi) * VD_ + nt * 8 + c0;
        size_t r1g = ((size_t)(b * N_ + row0 + 8) * HI_ + hi) * VD_ + nt * 8 + c0;
        float a0 = oacc[nt][0] * inv0, a1 = oacc[nt][1] * inv0;
        float a2 = oacc[nt][2] * inv1, a3 = oacc[nt][3] * inv1;
        __nv_bfloat16 h0 = __float2bfloat16(a0), h1 = __float2bfloat16(a1);
        __nv_bfloat16 h2 = __float2bfloat16(a2), h3 = __float2bfloat16(a3);
        __nv_bfloat162 hp0; hp0.x = h0; hp0.y = h1;
        __nv_bfloat162 hp1; hp1.x = h2; hp1.y = h3;
        *(uint32_t*)(oh + r0g) = *(uint32_t*)&hp0;
        *(uint32_t*)(ol + r0g) = packbf(a0 - __bfloat162float(h0), a1 - __bfloat162float(h1));
        *(uint32_t*)(oh + r1g) = *(uint32_t*)&hp1;
        *(uint32_t*)(ol + r1g) = packbf(a2 - __bfloat162float(h2), a3 - __bfloat162float(h3));
    }
}

// ---------------------------------------------------------------------------
// Launch
// ---------------------------------------------------------------------------
extern "C" void kernel_launch(void* const* d_in, const int* in_sizes, int n_in,
                              void* d_out, int out_size)
{
    const float* x  = (const float*)d_in[0];
    const float* Wq = (const float*)d_in[1];   // [2048, 4096]
    const float* Wk = (const float*)d_in[2];   // [2048, 1024]
    const float* Wv = (const float*)d_in[3];   // [2048, 1024]
    const float* Wo = (const float*)d_in[4];   // [4096, 2048]
    float* out = (float*)d_out;

    float* qkv;
    __nv_bfloat16 *xh, *xl, *wallh, *walll, *woh, *wol;
    __nv_bfloat16 *qh, *ql, *kh, *kl, *vh, *vl, *ah, *al;
    cudaGetSymbolAddress((void**)&qkv, g_qkv);
    cudaGetSymbolAddress((void**)&xh, g_xh);
    cudaGetSymbolAddress((void**)&xl, g_xl);
    cudaGetSymbolAddress((void**)&wallh, g_wallh);
    cudaGetSymbolAddress((void**)&walll, g_walll);
    cudaGetSymbolAddress((void**)&woh, g_woh);
    cudaGetSymbolAddress((void**)&wol, g_wol);
    cudaGetSymbolAddress((void**)&qh, g_qh);
    cudaGetSymbolAddress((void**)&ql, g_ql);
    cudaGetSymbolAddress((void**)&kh, g_kh);
    cudaGetSymbolAddress((void**)&kl, g_kl);
    cudaGetSymbolAddress((void**)&vh, g_vh);
    cudaGetSymbolAddress((void**)&vl, g_vl);
    cudaGetSymbolAddress((void**)&ah, g_ah);
    cudaGetSymbolAddress((void**)&al, g_al);

    const int M = B_ * N_;   // 2048

    // Splits: x plain; Wq/Wk/Wv concatenated into [2048, 6144]; Wo plain
    {
        int t = B_ * N_ * D_ / 4;
        split4_kernel<<<(t + 255) / 256, 256>>>((const float4*)x, xh, xl, t);
        t = D_ * 4096 / 4;
        splitcat4_kernel<<<(t + 255) / 256, 256>>>(Wq, wallh, walll, 4096, QKV_W, 0, t);
        t = D_ * 1024 / 4;
        splitcat4_kernel<<<(t + 255) / 256, 256>>>(Wk, wallh, walll, 1024, QKV_W, 4096, t);
        splitcat4_kernel<<<(t + 255) / 256, 256>>>(Wv, wallh, walll, 1024, QKV_W, 5120, t);
        t = 4096 * D_ / 4;
        split4_kernel<<<(t + 255) / 256, 256>>>((const float4*)Wo, woh, wol, t);
    }

    cudaFuncSetAttribute(bgemm3_kernel,
                         cudaFuncAttributeMaxDynamicSharedMemorySize,
                         GEMM_SMEM_BYTES);

    // Fused QKV projection: [2048, 2048] x [2048, 6144] -> qkv fp32
    bgemm3_kernel<<<dim3(QKV_W / 128, M / 128), 256, GEMM_SMEM_BYTES>>>(
        xh, xl, wallh, walll, qkv, M, QKV_W, D_);

    // Merged RoPE + split postproc; fold (1/sqrt(d))*log2(e) into q
    const float s2 = 0.08838834764831845f * 1.4426950408889634f;
    postproc_kernel<<<(PPTOT + 255) / 256, 256>>>(
        qkv, qh, ql, kh, kl, vh, vl, s2);

    cudaFuncSetAttribute(flash_mma_kernel,
                         cudaFuncAttributeMaxDynamicSharedMemorySize,
                         FLASH3_SMEM_BYTES);
    flash_mma_kernel<<<dim3(8, 64), 256, FLASH3_SMEM_BYTES>>>(
        qh, ql, kh, kl, vh, vl, ah, al);

    // Output projection: [2048, 4096] x [4096, 2048]
    bgemm3_kernel<<<dim3(2048 / 128, M / 128), 256, GEMM_SMEM_BYTES>>>(
        ah, al, woh, wol, out, M, 2048, 4096);
}

// round 17
// speedup vs baseline: 1.0230x; 1.0230x over previous
#include <cuda_runtime.h>
#include <cuda_bf16.h>
#include <math.h>
#include <stdint.h>

// Problem constants
#define B_   2
#define N_   1024
#define D_   2048
#define H_   8
#define I_   4
#define KD_  128
#define VD_  128
#define HI_  32    // H_*I_
#define QKV_W 6144  // 4096 q + 1024 k + 1024 v

// Postproc dispatch ranges
#define QTOT  (B_ * N_ * HI_ * 64)       // 4,194,304
#define KTOT  (B_ * N_ * H_ * 64)        // 1,048,576
#define VTOT4 (B_ * N_ * H_ * VD_ / 4)   //   524,288
#define PPTOT (QTOT + KTOT + VTOT4)

// ---------------------------------------------------------------------------
// Device scratch
// ---------------------------------------------------------------------------
__device__ float g_qkv[(size_t)B_ * N_ * QKV_W];          // fused q|k|v fp32
__device__ __nv_bfloat16 g_xh[(size_t)B_ * N_ * D_];
__device__ __nv_bfloat16 g_xl[(size_t)B_ * N_ * D_];
__device__ __nv_bfloat16 g_wallh[(size_t)D_ * QKV_W];     // fused Wq|Wk|Wv
__device__ __nv_bfloat16 g_walll[(size_t)D_ * QKV_W];
__device__ __nv_bfloat16 g_woh[(size_t)HI_ * VD_ * D_];
__device__ __nv_bfloat16 g_wol[(size_t)HI_ * VD_ * D_];
__device__ __nv_bfloat16 g_qh[(size_t)B_ * N_ * HI_ * KD_];
__device__ __nv_bfloat16 g_ql[(size_t)B_ * N_ * HI_ * KD_];
__device__ __nv_bfloat16 g_kh[(size_t)B_ * N_ * H_ * KD_];
__device__ __nv_bfloat16 g_kl[(size_t)B_ * N_ * H_ * KD_];
__device__ __nv_bfloat16 g_vh[(size_t)B_ * N_ * H_ * VD_];
__device__ __nv_bfloat16 g_vl[(size_t)B_ * N_ * H_ * VD_];
__device__ __nv_bfloat16 g_ah[(size_t)B_ * N_ * HI_ * VD_];
__device__ __nv_bfloat16 g_al[(size_t)B_ * N_ * HI_ * VD_];

// ---------------------------------------------------------------------------
// Helpers
// ---------------------------------------------------------------------------
__device__ __forceinline__ void ldsm4(uint32_t* r, const __nv_bfloat16* p) {
    uint32_t a = (uint32_t)__cvta_generic_to_shared(p);
    asm volatile("ldmatrix.sync.aligned.m8n8.x4.shared.b16 {%0,%1,%2,%3}, [%4];"
                 : "=r"(r[0]), "=r"(r[1]), "=r"(r[2]), "=r"(r[3]) : "r"(a));
}
__device__ __forceinline__ void ldsm4t(uint32_t* r, const __nv_bfloat16* p) {
    uint32_t a = (uint32_t)__cvta_generic_to_shared(p);
    asm volatile("ldmatrix.sync.aligned.m8n8.x4.trans.shared.b16 {%0,%1,%2,%3}, [%4];"
                 : "=r"(r[0]), "=r"(r[1]), "=r"(r[2]), "=r"(r[3]) : "r"(a));
}
__device__ __forceinline__ void mma16816(float* c, const uint32_t* a, const uint32_t* b) {
    asm volatile("mma.sync.aligned.m16n8k16.row.col.f32.bf16.bf16.f32 "
                 "{%0,%1,%2,%3}, {%4,%5,%6,%7}, {%8,%9}, {%0,%1,%2,%3};"
                 : "+f"(c[0]), "+f"(c[1]), "+f"(c[2]), "+f"(c[3])
                 : "r"(a[0]), "r"(a[1]), "r"(a[2]), "r"(a[3]),
                   "r"(b[0]), "r"(b[1]));
}
__device__ __forceinline__ uint32_t packbf(float a, float b) {
    __nv_bfloat162 t = __floats2bfloat162_rn(a, b);
    return *(uint32_t*)&t;
}
__device__ __forceinline__ void cp16s(uint32_t s, const void* g) {
    asm volatile("cp.async.cg.shared.global [%0], [%1], 16;" :: "r"(s), "l"(g));
}
#define CP_COMMIT() asm volatile("cp.async.commit_group;" ::: "memory")
#define CP_WAIT(n)  asm volatile("cp.async.wait_group %0;" :: "n"(n) : "memory")

// ---------------------------------------------------------------------------
// fp32 -> bf16 hi/lo split (coalesced: one float4 per thread)
// ---------------------------------------------------------------------------
__device__ __forceinline__ void split_one(float4 v, __nv_bfloat16* oh,
                                          __nv_bfloat16* ol, size_t o)
{
    __nv_bfloat16 h0 = __float2bfloat16(v.x);
    __nv_bfloat16 h1 = __float2bfloat16(v.y);
    __nv_bfloat16 h2 = __float2bfloat16(v.z);
    __nv_bfloat16 h3 = __float2bfloat16(v.w);
    __nv_bfloat162 hp0; hp0.x = h0; hp0.y = h1;
    __nv_bfloat162 hp1; hp1.x = h2; hp1.y = h3;
    *(uint2*)(oh + o) = make_uint2(*(uint32_t*)&hp0, *(uint32_t*)&hp1);
    *(uint2*)(ol + o) = make_uint2(
        packbf(v.x - __bfloat162float(h0), v.y - __bfloat162float(h1)),
        packbf(v.z - __bfloat162float(h2), v.w - __bfloat162float(h3)));
}

__global__ void split4_kernel(const float4* __restrict__ in,
                              __nv_bfloat16* __restrict__ oh,
                              __nv_bfloat16* __restrict__ ol, int total4)
{
    int i = blockIdx.x * blockDim.x + threadIdx.x;
    if (i >= total4) return;
    split_one(in[i], oh, ol, (size_t)i * 4);
}

// Split + place into wider fused matrix at column offset (coalesced)
__global__ void splitcat4_kernel(const float* __restrict__ in,
                                 __nv_bfloat16* __restrict__ oh,
                                 __nv_bfloat16* __restrict__ ol,
                                 int srcW, int dstW, int colofs, int total4)
{
    int i = blockIdx.x * blockDim.x + threadIdx.x;
    if (i >= total4) return;
    int w4  = srcW >> 2;
    int row = i / w4;
    int c4  = i - row * w4;
    float4 v = *(const float4*)(in + (size_t)row * srcW + c4 * 4);
    split_one(v, oh, ol, (size_t)row * dstW + colofs + c4 * 4);
}

// ---------------------------------------------------------------------------
// Split-bf16 GEMM, 3-stage cp.async pipeline (plain fp32 C store).
// BM=BN=128, BK=32, 256 threads, 8 warps (4m x 2n), warp tile 32x64.
// OCCUPANCY 2.
// ---------------------------------------------------------------------------
#define ASTR 40
#define BSTR 136
#define GSTAGE (128*ASTR*2 + 32*BSTR*2)          // bf16 elems per stage (18944)
#define GEMM_SMEM_BYTES (GSTAGE * 3 * 2)         // 113,664 B

__global__ __launch_bounds__(256, 2) void bgemm3_kernel(
    const __nv_bfloat16* __restrict__ Ah_g, const __nv_bfloat16* __restrict__ Al_g,
    const __nv_bfloat16* __restrict__ Bh_g, const __nv_bfloat16* __restrict__ Bl_g,
    float* __restrict__ C, int M, int Nc, int Kd)
{
    extern __shared__ __nv_bfloat16 sm[];

    const int tid    = threadIdx.x;
    const int lane   = tid & 31;
    const int wid    = tid >> 5;
    const int warp_m = wid & 3;
    const int warp_n = wid >> 2;
    const int brow   = blockIdx.y * 128;
    const int bcol   = blockIdx.x * 128;
    const int lr = lane & 15;
    const int lc = (lane >> 4) << 3;

    __nv_bfloat16* sAh[3]; __nv_bfloat16* sAl[3];
    __nv_bfloat16* sBh[3]; __nv_bfloat16* sBl[3];
    #pragma unroll
    for (int s = 0; s < 3; s++) {
        __nv_bfloat16* base = sm + s * GSTAGE;
        sAh[s] = base;
        sAl[s] = base + 128 * ASTR;
        sBh[s] = base + 128 * ASTR * 2;
        sBl[s] = base + 128 * ASTR * 2 + 32 * BSTR;
    }

    auto load_stage = [&](int s, int k0) {
        #pragma unroll
        for (int p = 0; p < 2; p++) {
            int i = p * 256 + tid;
            int r = i >> 2, cc = (i & 3) << 3;
            size_t g = (size_t)(brow + r) * Kd + k0 + cc;
            cp16s((uint32_t)__cvta_generic_to_shared(sAh[s] + r * ASTR + cc), Ah_g + g);
            cp16s((uint32_t)__cvta_generic_to_shared(sAl[s] + r * ASTR + cc), Al_g + g);
        }
        #pragma unroll
        for (int p = 0; p < 2; p++) {
            int i = p * 256 + tid;
            int r = i >> 4, cc = (i & 15) << 3;
            size_t g = (size_t)(k0 + r) * Nc + bcol + cc;
            cp16s((uint32_t)__cvta_generic_to_shared(sBh[s] + r * BSTR + cc), Bh_g + g);
            cp16s((uint32_t)__cvta_generic_to_shared(sBl[s] + r * BSTR + cc), Bl_g + g);
        }
    };

    float acc[2][8][4];
    #pragma unroll
    for (int im = 0; im < 2; im++)
        #pragma unroll
        for (int jn = 0; jn < 8; jn++)
            #pragma unroll
            for (int t = 0; t < 4; t++) acc[im][jn][t] = 0.f;

    const int nk = Kd >> 5;
    load_stage(0, 0);
    CP_COMMIT();
    load_stage(1, 32);
    CP_COMMIT();

    for (int kt = 0; kt < nk; kt++) {
        const int s = kt % 3;
        if (kt + 1 < nk) { CP_WAIT(1); } else { CP_WAIT(0); }
        __syncthreads();
        if (kt + 2 < nk) {
            load_stage((kt + 2) % 3, (kt + 2) << 5);
            CP_COMMIT();
        }

        #pragma unroll
        for (int ks = 0; ks < 2; ks++) {
            uint32_t ah[2][4], al[2][4];
            #pragma unroll
            for (int im = 0; im < 2; im++) {
                const int ar = (warp_m * 32 + im * 16 + lr) * ASTR + ks * 16 + lc;
                ldsm4(ah[im], sAh[s] + ar);
                ldsm4(al[im], sAl[s] + ar);
            }
            #pragma unroll
            for (int jp = 0; jp < 4; jp++) {
                uint32_t bh[4], bl[4];
                const int boff = (ks * 16 + lr) * BSTR + warp_n * 64 + jp * 16 + lc;
                ldsm4t(bh, sBh[s] + boff);
                ldsm4t(bl, sBl[s] + boff);
                #pragma unroll
                for (int im = 0; im < 2; im++) {
                    mma16816(acc[im][jp * 2 + 0], ah[im], bh + 0);
                    mma16816(acc[im][jp * 2 + 1], ah[im], bh + 2);
                    mma16816(acc[im][jp * 2 + 0], ah[im], bl + 0);
                    mma16816(acc[im][jp * 2 + 1], ah[im], bl + 2);
                    mma16816(acc[im][jp * 2 + 0], al[im], bh + 0);
                    mma16816(acc[im][jp * 2 + 1], al[im], bh + 2);
                }
            }
        }
    }

    const int r0 = lane >> 2;
    const int c0 = (lane & 3) << 1;
    #pragma unroll
    for (int im = 0; im < 2; im++) {
        #pragma unroll
        for (int jn = 0; jn < 8; jn++) {
            float* cp = C + (size_t)(brow + warp_m * 32 + im * 16 + r0) * Nc
                          + bcol + warp_n * 64 + jn * 8 + c0;
            *(float2*)cp              = make_float2(acc[im][jn][0], acc[im][jn][1]);
            *(float2*)(cp + 8 * (size_t)Nc) = make_float2(acc[im][jn][2], acc[im][jn][3]);
        }
    }
}

// ---------------------------------------------------------------------------
// Merged post-processing: RoPE+split for q and k, plain split for v.
// ---------------------------------------------------------------------------
__device__ __forceinline__ void rope_one(const float* __restrict__ qkv,
                                         __nv_bfloat16* __restrict__ oh,
                                         __nv_bfloat16* __restrict__ ol,
                                         int idx, int nheads, int colofs,
                                         float outscale)
{
    int j    = idx & 63;
    int t    = idx >> 6;
    int head = t % nheads;
    int row  = t / nheads;
    int n    = row & (N_ - 1);

    float inv = exp2f((float)j * -0.20762050593045889f);   // 10000^(-j/64)
    float ang = (float)n * inv;
    float s, c;
    sincosf(ang, &s, &c);

    const float* p = qkv + (size_t)row * QKV_W + colofs + head * 128;
    float x1 = p[j];
    float x2 = p[j + 64];
    float r1 = (x1 * c - x2 * s) * outscale;
    float r2 = (x1 * s + x2 * c) * outscale;

    size_t ob = ((size_t)row * nheads + head) * 128;
    __nv_bfloat16 h1 = __float2bfloat16(r1);
    __nv_bfloat16 h2 = __float2bfloat16(r2);
    oh[ob + j]      = h1;
    oh[ob + j + 64] = h2;
    ol[ob + j]      = __float2bfloat16(r1 - __bfloat162float(h1));
    ol[ob + j + 64] = __float2bfloat16(r2 - __bfloat162float(h2));
}

__global__ void postproc_kernel(const float* __restrict__ qkv,
                                __nv_bfloat16* __restrict__ qh,
                                __nv_bfloat16* __restrict__ ql,
                                __nv_bfloat16* __restrict__ kh,
                                __nv_bfloat16* __restrict__ kl,
                                __nv_bfloat16* __restrict__ vh,
                                __nv_bfloat16* __restrict__ vl,
                                float qscale)
{
    int gid = blockIdx.x * blockDim.x + threadIdx.x;
    if (gid < QTOT) {
        rope_one(qkv, qh, ql, gid, HI_, 0, qscale);
    } else if (gid < QTOT + KTOT) {
        rope_one(qkv, kh, kl, gid - QTOT, H_, 4096, 1.0f);
    } else if (gid < PPTOT) {
        int idx = gid - QTOT - KTOT;
        int row = idx >> 8;            // 256 float4 per v row (1024 floats)
        int c4  = (idx & 255) << 2;
        float4 v = *(const float4*)(qkv + (size_t)row * QKV_W + 5120 + c4);
        split_one(v, vh, vl, (size_t)row * 1024 + c4);
    }
}

// ---------------------------------------------------------------------------
// Tensor-core flash attention (HMMA). BM=64, BN=64, d=128, causal.
// 128 threads (4 warps x 16 rows), single KV buffer, OCCUPANCY 2:
// cross-CTA overlap fills load/barrier bubbles (smem 104,448 B/CTA).
// Per-row kv-tile sequence identical to BM=128 version -> bit-identical out.
// ---------------------------------------------------------------------------
#define QSTR 136
#define KSTR 136
#define VSTR 136
#define FLASH4_SMEM_BYTES ((2*64*QSTR + 4*64*136) * 2)    // 104,448 B

__global__ __launch_bounds__(128, 2) void flash_mma_kernel(
    const __nv_bfloat16* __restrict__ qh, const __nv_bfloat16* __restrict__ ql,
    const __nv_bfloat16* __restrict__ kh, const __nv_bfloat16* __restrict__ kl,
    const __nv_bfloat16* __restrict__ vh, const __nv_bfloat16* __restrict__ vl,
    __nv_bfloat16* __restrict__ oh, __nv_bfloat16* __restrict__ ol)
{
    extern __shared__ __nv_bfloat16 smb[];
    __nv_bfloat16* QH  = smb;                 // 64 x 136
    __nv_bfloat16* QL  = QH + 64 * QSTR;
    __nv_bfloat16* KV0 = QL + 64 * QSTR;      // KH|KL|VH|VL, each 64 x 136

    const int tid  = threadIdx.x;
    const int lane = tid & 31;
    const int w    = tid >> 5;                // 0..3
    const int qt   = gridDim.x - 1 - blockIdx.x;   // 0..15, heavy first
    const int bhi  = blockIdx.y;
    const int b    = bhi >> 5;
    const int hi   = bhi & 31;
    const int h    = hi >> 2;

    const int lr = lane & 15;
    const int lc = (lane >> 4) << 3;
    const uint32_t kvu = (uint32_t)__cvta_generic_to_shared(KV0);

    const uint32_t KLOFS = 64 * 136 * 2;      // bytes
    const uint32_t VHOFS = 2 * KLOFS;
    const uint32_t VLOFS = 3 * KLOFS;

    auto load_kv = [&](int kt) {
        #pragma unroll
        for (int p = 0; p < 8; p++) {
            int i = p * 128 + tid;            // 0..1023
            int r = i >> 4, cb = (i & 15) << 4;
            size_t g = ((size_t)(b * N_ + kt * 64 + r) * H_ + h) * 128 + (cb >> 1);
            uint32_t bs = kvu + r * 272 + cb;
            cp16s(bs, kh + g);
            cp16s(bs + KLOFS, kl + g);
            cp16s(bs + VHOFS, vh + g);
            cp16s(bs + VLOFS, vl + g);
        }
    };

    // Kick off first KV load, then fill Q while it flies.
    load_kv(0);
    CP_COMMIT();

    const size_t qrow0 = (size_t)(b * N_ + qt * 64) * HI_ + hi;
    for (int i = tid; i < 64 * 16; i += 128) {
        int r = i >> 4, cb = i & 15;
        size_t g = (qrow0 + (size_t)r * HI_) * KD_;
        *(uint4*)(QH + r * QSTR + cb * 8) = *((const uint4*)(qh + g) + cb);
        *(uint4*)(QL + r * QSTR + cb * 8) = *((const uint4*)(ql + g) + cb);
    }

    float m0 = -1e30f, m1 = -1e30f, l0 = 0.f, l1 = 0.f;
    float oacc[16][4];
    #pragma unroll
    for (int nt = 0; nt < 16; nt++)
        #pragma unroll
        for (int t = 0; t < 4; t++) oacc[nt][t] = 0.f;

    const int row0 = qt * 64 + w * 16 + (lane >> 2);

    __nv_bfloat16* KH = KV0;
    __nv_bfloat16* KL = KH + 64 * 136;
    __nv_bfloat16* VH = KL + 64 * 136;
    __nv_bfloat16* VL = VH + 64 * 136;

    for (int kt = 0; kt <= qt; kt++) {
        CP_WAIT(0);
        __syncthreads();

        {
            float sacc[8][4];
            #pragma unroll
            for (int j = 0; j < 8; j++)
                #pragma unroll
                for (int t = 0; t < 4; t++) sacc[j][t] = 0.f;

            #pragma unroll
            for (int ks = 0; ks < 8; ks++) {
                uint32_t ah[4], al[4];
                ldsm4(ah, &QH[(w * 16 + lr) * QSTR + ks * 16 + lc]);
                ldsm4(al, &QL[(w * 16 + lr) * QSTR + ks * 16 + lc]);
                #pragma unroll
                for (int nb = 0; nb < 4; nb++) {
                    uint32_t bhk[4], blk[4];
                    ldsm4(bhk, &KH[(nb * 16 + lr) * KSTR + ks * 16 + lc]);
                    ldsm4(blk, &KL[(nb * 16 + lr) * KSTR + ks * 16 + lc]);
                    uint32_t beh[2] = {bhk[0], bhk[2]};
                    uint32_t boh[2] = {bhk[1], bhk[3]};
                    uint32_t bel[2] = {blk[0], blk[2]};
                    uint32_t bol[2] = {blk[1], blk[3]};
                    mma16816(sacc[2 * nb + 0], ah, beh);
                    mma16816(sacc[2 * nb + 0], al, beh);
                    mma16816(sacc[2 * nb + 0], ah, bel);
                    mma16816(sacc[2 * nb + 1], ah, boh);
                    mma16816(sacc[2 * nb + 1], al, boh);
                    mma16816(sacc[2 * nb + 1], ah, bol);
                }
            }

            if (kt == qt) {
                #pragma unroll
                for (int j = 0; j < 8; j++) {
                    int col = kt * 64 + j * 8 + 2 * (lane & 3);
                    if (col     > row0)     sacc[j][0] = -1e30f;
                    if (col + 1 > row0)     sacc[j][1] = -1e30f;
                    if (col     > row0 + 8) sacc[j][2] = -1e30f;
                    if (col + 1 > row0 + 8) sacc[j][3] = -1e30f;
                }
            }

            float tm0 = -1e30f, tm1 = -1e30f;
            #pragma unroll
            for (int j = 0; j < 8; j++) {
                tm0 = fmaxf(tm0, fmaxf(sacc[j][0], sacc[j][1]));
                tm1 = fmaxf(tm1, fmaxf(sacc[j][2], sacc[j][3]));
            }
            tm0 = fmaxf(tm0, __shfl_xor_sync(0xffffffffu, tm0, 1));
            tm0 = fmaxf(tm0, __shfl_xor_sync(0xffffffffu, tm0, 2));
            tm1 = fmaxf(tm1, __shfl_xor_sync(0xffffffffu, tm1, 1));
            tm1 = fmaxf(tm1, __shfl_xor_sync(0xffffffffu, tm1, 2));

            float mn0 = fmaxf(m0, tm0), mn1 = fmaxf(m1, tm1);
            float al0 = exp2f(m0 - mn0), al1 = exp2f(m1 - mn1);
            m0 = mn0; m1 = mn1;

            float rs0 = 0.f, rs1 = 0.f;
            uint32_t pah[4][4], pal[4][4];
            #pragma unroll
            for (int j = 0; j < 8; j++) {
                float p0 = exp2f(sacc[j][0] - mn0);
                float p1 = exp2f(sacc[j][1] - mn0);
                float p2 = exp2f(sacc[j][2] - mn1);
                float p3 = exp2f(sacc[j][3] - mn1);
                rs0 += p0 + p1;
                rs1 += p2 + p3;
                __nv_bfloat16 h0 = __float2bfloat16(p0);
                __nv_bfloat16 h1 = __float2bfloat16(p1);
                __nv_bfloat16 h2 = __float2bfloat16(p2);
                __nv_bfloat16 h3 = __float2bfloat16(p3);
                int kk = j >> 1, odd = j & 1;
                __nv_bfloat162 ph01; ph01.x = h0; ph01.y = h1;
                __nv_bfloat162 ph23; ph23.x = h2; ph23.y = h3;
                pah[kk][odd * 2 + 0] = *(uint32_t*)&ph01;
                pah[kk][odd * 2 + 1] = *(uint32_t*)&ph23;
                pal[kk][odd * 2 + 0] = packbf(p0 - __bfloat162float(h0),
                                              p1 - __bfloat162float(h1));
                pal[kk][odd * 2 + 1] = packbf(p2 - __bfloat162float(h2),
                                              p3 - __bfloat162float(h3));
            }
            rs0 += __shfl_xor_sync(0xffffffffu, rs0, 1);
            rs0 += __shfl_xor_sync(0xffffffffu, rs0, 2);
            rs1 += __shfl_xor_sync(0xffffffffu, rs1, 1);
            rs1 += __shfl_xor_sync(0xffffffffu, rs1, 2);
            l0 = al0 * l0 + rs0;
            l1 = al1 * l1 + rs1;

            #pragma unroll
            for (int nt = 0; nt < 16; nt++) {
                oacc[nt][0] *= al0; oacc[nt][1] *= al0;
                oacc[nt][2] *= al1; oacc[nt][3] *= al1;
            }

            #pragma unroll
            for (int kk = 0; kk < 4; kk++) {
                #pragma unroll
                for (int jp = 0; jp < 8; jp++) {
                    uint32_t vhr[4], vlr[4];
                    ldsm4t(vhr, &VH[(kk * 16 + lr) * VSTR + jp * 16 + lc]);
                    ldsm4t(vlr, &VL[(kk * 16 + lr) * VSTR + jp * 16 + lc]);
                    mma16816(oacc[2 * jp + 0], pah[kk], vhr + 0);
                    mma16816(oacc[2 * jp + 0], pal[kk], vhr + 0);
                    mma16816(oacc[2 * jp + 0], pah[kk], vlr + 0);
                    mma16816(oacc[2 * jp + 1], pah[kk], vhr + 2);
                    mma16816(oacc[2 * jp + 1], pal[kk], vhr + 2);
                    mma16816(oacc[2 * jp + 1], pah[kk], vlr + 2);
                }
            }
        }

        // All warps done reading this KV tile before overwriting it.
        if (kt < qt) {
            __syncthreads();
            load_kv(kt + 1);
            CP_COMMIT();
        }
    }

    float inv0 = 1.f / l0, inv1 = 1.f / l1;
    const int c0 = 2 * (lane & 3);
    #pragma unroll
    for (int nt = 0; nt < 16; nt++) {
        size_t r0g = ((size_t)(b * N_ + row0) * HI_ + hi) * VD_ + nt * 8 + c0;
        size_t r1g = ((size_t)(b * N_ + row0 + 8) * HI_ + hi) * VD_ + nt * 8 + c0;
        float a0 = oacc[nt][0] * inv0, a1 = oacc[nt][1] * inv0;
        float a2 = oacc[nt][2] * inv1, a3 = oacc[nt][3] * inv1;
        __nv_bfloat16 h0 = __float2bfloat16(a0), h1 = __float2bfloat16(a1);
        __nv_bfloat16 h2 = __float2bfloat16(a2), h3 = __float2bfloat16(a3);
        __nv_bfloat162 hp0; hp0.x = h0; hp0.y = h1;
        __nv_bfloat162 hp1; hp1.x = h2; hp1.y = h3;
        *(uint32_t*)(oh + r0g) = *(uint32_t*)&hp0;
        *(uint32_t*)(ol + r0g) = packbf(a0 - __bfloat162float(h0), a1 - __bfloat162float(h1));
        *(uint32_t*)(oh + r1g) = *(uint32_t*)&hp1;
        *(uint32_t*)(ol + r1g) = packbf(a2 - __bfloat162float(h2), a3 - __bfloat162float(h3));
    }
}

// ---------------------------------------------------------------------------
// Launch
// ---------------------------------------------------------------------------
extern "C" void kernel_launch(void* const* d_in, const int* in_sizes, int n_in,
                              void* d_out, int out_size)
{
    const float* x  = (const float*)d_in[0];
    const float* Wq = (const float*)d_in[1];   // [2048, 4096]
    const float* Wk = (const float*)d_in[2];   // [2048, 1024]
    const float* Wv = (const float*)d_in[3];   // [2048, 1024]
    const float* Wo = (const float*)d_in[4];   // [4096, 2048]
    float* out = (float*)d_out;

    float* qkv;
    __nv_bfloat16 *xh, *xl, *wallh, *walll, *woh, *wol;
    __nv_bfloat16 *qh, *ql, *kh, *kl, *vh, *vl, *ah, *al;
    cudaGetSymbolAddress((void**)&qkv, g_qkv);
    cudaGetSymbolAddress((void**)&xh, g_xh);
    cudaGetSymbolAddress((void**)&xl, g_xl);
    cudaGetSymbolAddress((void**)&wallh, g_wallh);
    cudaGetSymbolAddress((void**)&walll, g_walll);
    cudaGetSymbolAddress((void**)&woh, g_woh);
    cudaGetSymbolAddress((void**)&wol, g_wol);
    cudaGetSymbolAddress((void**)&qh, g_qh);
    cudaGetSymbolAddress((void**)&ql, g_ql);
    cudaGetSymbolAddress((void**)&kh, g_kh);
    cudaGetSymbolAddress((void**)&kl, g_kl);
    cudaGetSymbolAddress((void**)&vh, g_vh);
    cudaGetSymbolAddress((void**)&vl, g_vl);
    cudaGetSymbolAddress((void**)&ah, g_ah);
    cudaGetSymbolAddress((void**)&al, g_al);

    const int M = B_ * N_;   // 2048

    // Splits: x plain; Wq/Wk/Wv concatenated into [2048, 6144]; Wo plain
    {
        int t = B_ * N_ * D_ / 4;
        split4_kernel<<<(t + 255) / 256, 256>>>((const float4*)x, xh, xl, t);
        t = D_ * 4096 / 4;
        splitcat4_kernel<<<(t + 255) / 256, 256>>>(Wq, wallh, walll, 4096, QKV_W, 0, t);
        t = D_ * 1024 / 4;
        splitcat4_kernel<<<(t + 255) / 256, 256>>>(Wk, wallh, walll, 1024, QKV_W, 4096, t);
        splitcat4_kernel<<<(t + 255) / 256, 256>>>(Wv, wallh, walll, 1024, QKV_W, 5120, t);
        t = 4096 * D_ / 4;
        split4_kernel<<<(t + 255) / 256, 256>>>((const float4*)Wo, woh, wol, t);
    }

    cudaFuncSetAttribute(bgemm3_kernel,
                         cudaFuncAttributeMaxDynamicSharedMemorySize,
                         GEMM_SMEM_BYTES);

    // Fused QKV projection: [2048, 2048] x [2048, 6144] -> qkv fp32
    bgemm3_kernel<<<dim3(QKV_W / 128, M / 128), 256, GEMM_SMEM_BYTES>>>(
        xh, xl, wallh, walll, qkv, M, QKV_W, D_);

    // Merged RoPE + split postproc; fold (1/sqrt(d))*log2(e) into q
    const float s2 = 0.08838834764831845f * 1.4426950408889634f;
    postproc_kernel<<<(PPTOT + 255) / 256, 256>>>(
        qkv, qh, ql, kh, kl, vh, vl, s2);

    cudaFuncSetAttribute(flash_mma_kernel,
                         cudaFuncAttributeMaxDynamicSharedMemorySize,
                         FLASH4_SMEM_BYTES);
    flash_mma_kernel<<<dim3(16, 64), 128, FLASH4_SMEM_BYTES>>>(
        qh, ql, kh, kl, vh, vl, ah, al);

    // Output projection: [2048, 4096] x [4096, 2048]
    bgemm3_kernel<<<dim3(2048 / 128, M / 128), 256, GEMM_SMEM_BYTES>>>(
        ah, al, woh, wol, out, M, 2048, 4096);
}